// round 10
// baseline (speedup 1.0000x reference)
#include <cuda_runtime.h>
#include <cstdint>
#include <cstddef>

// BacklashNet chunk-parallel scan: persistent blocks, barrier-free warp-level
// boundary exchange, interval collapse.
//   lo = fl(fl(m_lo*x) + fl(m_lo*c_lo)), upx = fl(m_up*x), ub = fl(upx + k_up)
//   f1 = (prev >= lo);  f2 = (fl(prev - upx) <= k_up)
//   out = f1 ? (f2 ? fl(fl(lo+upx)+k_up) : lo) : (f2 ? ub : prev)
// Identity branch needs prev in (ub*, lo): interval-tracked until it provably
// collapses to one value -> chunk outputs become state-independent.

#define NT    512         // threads per block = chunks per row
#define NW    16          // warps per block
#define CL    16          // steps per chunk (T = NT*CL = 8192)
#define PAD   20          // smem floats per chunk: 80B stride, 16B aligned;
                          //   conflict-free for 128-bit LDS/STS
#define WREG  512         // floats per warp region (32 lanes * CL)
#define MAXI  8           // max rows per persistent block (B<=MAXI*grid)
#define PBLK  444         // persistent grid: 148 SMs * 3 blocks

struct Wt { float m_lo, m_up, k_lo, k_up; };

__device__ __forceinline__ uint32_t smem_u32(const void* p) {
    return (uint32_t)__cvta_generic_to_shared(p);
}
__device__ __forceinline__ void cp_async16(uint32_t dst, const float* src) {
    asm volatile("cp.async.ca.shared.global [%0], [%1], 16;\n" :: "r"(dst), "l"(src));
}
__device__ __forceinline__ void post_u64(unsigned long long* slot, float v) {
    unsigned long long pk = (1ull << 32) | (unsigned long long)__float_as_uint(v);
    asm volatile("st.volatile.shared.b64 [%0], %1;" :: "r"(smem_u32(slot)), "l"(pk));
}
__device__ __forceinline__ unsigned long long ld_u64_vol(const unsigned long long* slot) {
    unsigned long long v;
    asm volatile("ld.volatile.shared.b64 %0, [%1];" : "=l"(v) : "r"(smem_u32(slot)));
    return v;
}

__device__ __forceinline__ bool f2_pred(float p, float upx, float k_up) {
    return __fadd_rn(p, -upx) <= k_up;          // fl(p - upx) <= k_up (monotone in p)
}
__device__ __forceinline__ void mkconst(const Wt& w, float xv,
                                        float& lo, float& upx, float& ub, float& v1) {
    float mlx = __fmul_rn(w.m_lo, xv);
    upx = __fmul_rn(w.m_up, xv);
    lo  = __fadd_rn(mlx, w.k_lo);
    ub  = __fadd_rn(upx, w.k_up);
    v1  = __fadd_rn(__fadd_rn(lo, upx), w.k_up); // reference's left-assoc sum
}
__device__ __forceinline__ float step1(float p, float lo, float upx, float ub,
                                       float v1, float k_up) {
    bool f1 = (p >= lo);
    bool f2 = f2_pred(p, upx, k_up);
    float a = f2 ? v1 : lo;
    float b = f2 ? ub : p;
    return f1 ? a : b;
}

__global__ __launch_bounds__(NT, 3)
void backlash_persist(const float* __restrict__ x,
                      const float* __restrict__ p0,
                      const float* __restrict__ wv,
                      float* __restrict__ out, int T, int B)
{
    __shared__ float s_buf[NT * PAD];                 // warp-local chunk data
    __shared__ unsigned long long s_post[MAXI * NW];  // (row_iter, warp) boundary

    const int k    = threadIdx.x;
    const int wid  = k >> 5;
    const int lane = k & 31;

    if (k < MAXI * NW) s_post[k] = 0ull;

    Wt w;
    w.m_lo = wv[0];
    w.m_up = wv[1];
    w.k_lo = __fmul_rn(w.m_lo, wv[2]);
    w.k_up = __fmul_rn(w.m_up, wv[3]);
    __syncthreads();                                  // only block barrier

    float* xc = s_buf + k * PAD;                      // this thread's chunk
    const float INF = __int_as_float(0x7f800000);
    const unsigned FULL = 0xffffffffu;

    int i = 0;
    for (int row = blockIdx.x; row < B; row += gridDim.x, ++i) {
        // ---- Warp-local coalesced staged load ----
        {
            const float* src = x + (size_t)row * T + wid * WREG;
            const uint32_t sb = smem_u32(s_buf);
            #pragma unroll
            for (int q = 0; q < 4; ++q) {
                int tl = q * 128 + lane * 4;
                int c  = wid * 32 + (tl >> 4);
                int o  = tl & 15;
                cp_async16(sb + (uint32_t)(c * PAD + o) * 4u, src + tl);
            }
            asm volatile("cp.async.commit_group;\n" ::: "memory");
            asm volatile("cp.async.wait_group 0;\n" ::: "memory");
            __syncwarp();
        }

        // ---- Phase 1a: interval scan until collapse ----
        float A = -INF, Bv = INF;
        float p = 0.0f;
        bool  done = false;
        int   s = CL;

        #pragma unroll 1
        for (int t4 = 0; t4 < CL && !done; t4 += 4) {
            float4 qv = *(const float4*)(xc + t4);
            float xs[4] = {qv.x, qv.y, qv.z, qv.w};
            #pragma unroll
            for (int j = 0; j < 4; ++j) {
                if (!done) {
                    float lo, upx, ub, v1;
                    mkconst(w, xs[j], lo, upx, ub, v1);
                    // Region reachability over [A,Bv] via exact predicate evals.
                    // ps = fminf(Bv, lo): conservative (<=1 ulp) identity hull
                    // top; survival test at ps can only over-keep (sound).
                    float mAlo = fmaxf(A, lo);
                    float ps   = fminf(Bv, lo);
                    bool f2m = f2_pred(mAlo, upx, w.k_up);
                    bool f2B = f2_pred(Bv,   upx, w.k_up);
                    bool f2A = f2_pred(A,    upx, w.k_up);
                    bool f2s = f2_pred(ps,   upx, w.k_up);
                    bool aL  = (A < lo);
                    bool c1 = (mAlo <= Bv) &&  f2m;   // f1& f2 -> v1
                    bool c2 = (Bv >= lo)   && !f2B;   // f1&!f2 -> lo
                    bool c3 = aL           &&  f2A;   //!f1& f2 -> ub
                    bool c4 = aL           && !f2s;   // identity survives
                    float nA = INF, nB = -INF;
                    if (c1) { nA = fminf(nA, v1); nB = fmaxf(nB, v1); }
                    if (c2) { nA = fminf(nA, lo); nB = fmaxf(nB, lo); }
                    if (c3) { nA = fminf(nA, ub); nB = fmaxf(nB, ub); }
                    if (c4) { nA = fminf(nA, A);  nB = fmaxf(nB, ps); }
                    A = nA; Bv = nB;
                    if (A == Bv) { done = true; p = A; s = t4 + j; }
                }
            }
        }

        // ---- Phase 1b: concrete scan, in-place stores (t >= s) ----
        if (done) {
            xc[s] = p;
            int u = s + 1;
            for (; u < CL && (u & 3); ++u) {
                float lo, upx, ub, v1;
                mkconst(w, xc[u], lo, upx, ub, v1);
                p = step1(p, lo, upx, ub, v1, w.k_up);
                xc[u] = p;
            }
            #pragma unroll 1
            for (; u < CL; u += 4) {
                float4 qv = *(const float4*)(xc + u);
                float lo, upx, ub, v1;
                mkconst(w, qv.x, lo, upx, ub, v1);
                float o0 = step1(p,  lo, upx, ub, v1, w.k_up);
                mkconst(w, qv.y, lo, upx, ub, v1);
                float o1 = step1(o0, lo, upx, ub, v1, w.k_up);
                mkconst(w, qv.z, lo, upx, ub, v1);
                float o2 = step1(o1, lo, upx, ub, v1, w.k_up);
                mkconst(w, qv.w, lo, upx, ub, v1);
                float o3 = step1(o2, lo, upx, ub, v1, w.k_up);
                p = o3;
                *(float4*)(xc + u) = make_float4(o0, o1, o2, o3);
            }
        }

        // ---- Boundary exchange (no block barrier) ----
        // Collapsed end value is state-independent: post as soon as we have it.
        if (lane == 31 && done && wid < NW - 1)
            post_u64(&s_post[i * NW + wid], p);

        float bound;
        if (wid == 0) {
            bound = p0[row];
        } else {
            const unsigned long long* slot = &s_post[i * NW + wid - 1];
            unsigned long long v = ld_u64_vol(slot);
            while ((unsigned)(v >> 32) == 0u) v = ld_u64_vol(slot);
            bound = __uint_as_float((unsigned)v);
        }

        float pin = __shfl_up_sync(FULL, p, 1);
        if (lane == 0) pin = bound;

        unsigned ball = __ballot_sync(FULL, done);
        if (ball != FULL) {
            // Rare: fix uncollapsed lanes in increasing order.
            unsigned und = ~ball;
            while (und) {
                int l = __ffs(und) - 1; und &= und - 1;
                if (lane == l) {               // replay full chunk, write outputs
                    float pp = pin;
                    for (int t = 0; t < CL; ++t) {
                        float lo, upx, ub, v1;
                        mkconst(w, xc[t], lo, upx, ub, v1);
                        pp = step1(pp, lo, upx, ub, v1, w.k_up);
                        xc[t] = pp;
                    }
                    p = pp; s = 0;             // outputs complete; skip phase 3
                }
                float cvl = __shfl_sync(FULL, p, l);
                if (lane == l + 1) pin = cvl;
            }
            if (lane == 31 && !done && wid < NW - 1)
                post_u64(&s_post[i * NW + wid], p);
        }

        // ---- Phase 3: replay pre-collapse prefix (per-thread bound) ----
        for (int t4 = 0; t4 < s; t4 += 4) {
            float4 qv = *(const float4*)(xc + t4);  // t>=s lanes are outputs, unused
            float xs[4] = {qv.x, qv.y, qv.z, qv.w};
            #pragma unroll
            for (int j = 0; j < 4; ++j) {
                if (t4 + j < s) {
                    float lo, upx, ub, v1;
                    mkconst(w, xs[j], lo, upx, ub, v1);
                    pin = step1(pin, lo, upx, ub, v1, w.k_up);
                    xc[t4 + j] = pin;
                }
            }
        }

        // ---- Warp-local coalesced store ----
        __syncwarp();
        {
            float* dst = out + (size_t)row * T + wid * WREG;
            #pragma unroll
            for (int q = 0; q < 4; ++q) {
                int tl = q * 128 + lane * 4;
                int c  = wid * 32 + (tl >> 4);
                int o  = tl & 15;
                float4 v = *(const float4*)(s_buf + c * PAD + o);
                *(float4*)(dst + tl) = v;
            }
        }
        __syncwarp();
    }
}

extern "C" void kernel_launch(void* const* d_in, const int* in_sizes, int n_in,
                              void* d_out, int out_size)
{
    const float* x  = (const float*)d_in[0];  // (B, T, 1) fp32
    const float* p0 = (const float*)d_in[1];  // (B, 1, 1) fp32
    const float* wv = (const float*)d_in[2];  // (4,)      fp32
    float* out = (float*)d_out;

    const int B = in_sizes[1];      // 2048
    const int T = in_sizes[0] / B;  // 8192  (= NT * CL)

    int grid = (B < PBLK) ? B : PBLK;           // rows/block <= MAXI
    backlash_persist<<<grid, NT>>>(x, p0, wv, out, T, B);
}

// round 11
// speedup vs baseline: 1.0559x; 1.0559x over previous
#include <cuda_runtime.h>
#include <cstdint>
#include <cstddef>

// BacklashNet chunk-parallel scan: warp-decoupled SMEM staging, interval collapse.
//   lo = fl(fl(m_lo*x) + fl(m_lo*c_lo)), upx = fl(m_up*x), ub = fl(upx + k_up)
//   f1 = (prev >= lo);  f2 = (fl(prev - upx) <= k_up)
//   out = f1 ? (f2 ? fl(fl(lo+upx)+k_up) : lo) : (f2 ? ub : prev)
// Identity branch needs prev in (ub*, lo): interval-tracked until it provably
// collapses to one value -> chunk outputs become state-independent.

#define NT   512          // threads per block = chunks per row
#define CL   16           // steps per chunk (T = NT*CL = 8192)
#define PAD  20           // smem floats per chunk: 80B stride, 16B aligned;
                          //   conflict-free for 128-bit LDS/STS; slots [16..19]
#define WREG 512          // floats per warp region (32 lanes * CL)

struct Wt { float m_lo, m_up, k_lo, k_up; };

__device__ __forceinline__ uint32_t smem_u32(const void* p) {
    return (uint32_t)__cvta_generic_to_shared(p);
}
__device__ __forceinline__ void cp_async16(uint32_t dst, const float* src) {
    asm volatile("cp.async.ca.shared.global [%0], [%1], 16;\n" :: "r"(dst), "l"(src));
}

__device__ __forceinline__ bool f2_pred(float p, float upx, float k_up) {
    return __fadd_rn(p, -upx) <= k_up;          // fl(p - upx) <= k_up (monotone in p)
}
__device__ __forceinline__ void mkconst(const Wt& w, float xv,
                                        float& lo, float& upx, float& ub, float& v1) {
    float mlx = __fmul_rn(w.m_lo, xv);
    upx = __fmul_rn(w.m_up, xv);
    lo  = __fadd_rn(mlx, w.k_lo);
    ub  = __fadd_rn(upx, w.k_up);
    v1  = __fadd_rn(__fadd_rn(lo, upx), w.k_up); // reference's left-assoc sum
}
__device__ __forceinline__ float step1(float p, float lo, float upx, float ub,
                                       float v1, float k_up) {
    bool f1 = (p >= lo);
    bool f2 = f2_pred(p, upx, k_up);
    float a = f2 ? v1 : lo;
    float b = f2 ? ub : p;
    return f1 ? a : b;
}

__global__ __launch_bounds__(NT, 3)
void backlash_chunks(const float* __restrict__ x,
                     const float* __restrict__ p0,
                     const float* __restrict__ wv,
                     float* __restrict__ out, int T)
{
    __shared__ float s_buf[NT * PAD];   // chunk data + pad slots:
                                        //   xc[16]=cv  xc[17]=sx(int)  xc[18]=in

    const int k    = threadIdx.x;
    const int wid  = k >> 5;            // warp id (0..15)
    const int lane = k & 31;

    Wt w;
    w.m_lo = wv[0];
    w.m_up = wv[1];
    w.k_lo = __fmul_rn(w.m_lo, wv[2]);
    w.k_up = __fmul_rn(w.m_up, wv[3]);

    const size_t rowbase = (size_t)blockIdx.x * T;

    // ---- Warp-local coalesced staged load: warp w owns chunks [32w, 32w+32) ----
    {
        const float* src = x + rowbase + wid * WREG;
        const uint32_t sb = smem_u32(s_buf);
        #pragma unroll
        for (int i = 0; i < 4; ++i) {
            int tl = i * 128 + lane * 4;            // [0, 512) within warp region
            int c  = wid * 32 + (tl >> 4);
            int o  = tl & 15;
            cp_async16(sb + (uint32_t)(c * PAD + o) * 4u, src + tl);
        }
        asm volatile("cp.async.commit_group;\n" ::: "memory");
        asm volatile("cp.async.wait_group 0;\n" ::: "memory");
        __syncwarp();   // make cp.async data visible across the warp's lanes
    }

    float* xc = s_buf + k * PAD;        // this thread's chunk (in; becomes out)
    const float INF = __int_as_float(0x7f800000);

    // ---- Phase 1a: interval scan until collapse (float4 group loads, no stores) ----
    float A = -INF, Bv = INF;
    float p = 0.0f;
    bool  done = false;
    int   s = CL;

    #pragma unroll 1
    for (int t4 = 0; t4 < CL && !done; t4 += 4) {
        float4 q = *(const float4*)(xc + t4);
        float xs[4] = {q.x, q.y, q.z, q.w};
        #pragma unroll
        for (int j = 0; j < 4; ++j) {
            if (!done) {
                float lo, upx, ub, v1;
                mkconst(w, xs[j], lo, upx, ub, v1);
                // Region reachability over [A,Bv] via exact predicate evals.
                // ps = fminf(Bv, lo): conservative (<=1 ulp) identity hull top;
                // survival test at ps can only over-keep (sound).
                float mAlo = fmaxf(A, lo);
                float ps   = fminf(Bv, lo);
                bool aL = (A < lo);
                bool c1 = (mAlo <= Bv) &&  f2_pred(mAlo, upx, w.k_up); // f1& f2 -> v1
                bool c2 = (Bv >= lo)   && !f2_pred(Bv,   upx, w.k_up); // f1&!f2 -> lo
                bool c3 = aL           &&  f2_pred(A,    upx, w.k_up); //!f1& f2 -> ub
                bool c4 = aL           && !f2_pred(ps,   upx, w.k_up); // identity
                float nA = INF, nB = -INF;
                if (c1) { nA = fminf(nA, v1); nB = fmaxf(nB, v1); }
                if (c2) { nA = fminf(nA, lo); nB = fmaxf(nB, lo); }
                if (c3) { nA = fminf(nA, ub); nB = fmaxf(nB, ub); }
                if (c4) { nA = fminf(nA, A);  nB = fmaxf(nB, ps); }
                A = nA; Bv = nB;
                if (A == Bv) { done = true; p = A; s = t4 + j; }
            }
        }
    }

    // ---- Phase 1b: concrete scan, unconditional in-place stores (t >= s) ----
    if (done) {
        xc[s] = p;
        int u = s + 1;
        for (; u < CL && (u & 3); ++u) {           // align to float4
            float lo, upx, ub, v1;
            mkconst(w, xc[u], lo, upx, ub, v1);
            p = step1(p, lo, upx, ub, v1, w.k_up);
            xc[u] = p;
        }
        #pragma unroll 1
        for (; u < CL; u += 4) {
            float4 q = *(const float4*)(xc + u);
            float lo, upx, ub, v1;
            mkconst(w, q.x, lo, upx, ub, v1);
            float o0 = step1(p,  lo, upx, ub, v1, w.k_up);
            mkconst(w, q.y, lo, upx, ub, v1);
            float o1 = step1(o0, lo, upx, ub, v1, w.k_up);
            mkconst(w, q.z, lo, upx, ub, v1);
            float o2 = step1(o1, lo, upx, ub, v1, w.k_up);
            mkconst(w, q.w, lo, upx, ub, v1);
            float o3 = step1(o2, lo, upx, ub, v1, w.k_up);
            p = o3;
            *(float4*)(xc + u) = make_float4(o0, o1, o2, o3);
        }
    }

    // ---- Phase 2: inter-chunk resolution (pad-slot side channel) ----
    xc[16] = p;                                  // collapsed end value
    reinterpret_cast<int*>(xc)[17] = s;          // collapse index
    bool all = (bool)__syncthreads_and((int)done);   // block-uniform barrier
    float pin;
    if (all) {
        pin = (k == 0) ? p0[blockIdx.x] : s_buf[(k - 1) * PAD + 16];
    } else {
        if (k == 0) {                             // rare serial fallback
            float prev = p0[blockIdx.x];
            for (int c = 0; c < NT; ++c) {
                float* xr = s_buf + c * PAD;
                xr[18] = prev;
                if (reinterpret_cast<int*>(xr)[17] < CL) {
                    prev = xr[16];
                } else {                          // chunk input untouched
                    for (int tt = 0; tt < CL; ++tt) {
                        float lo, upx, ub, v1;
                        mkconst(w, xr[tt], lo, upx, ub, v1);
                        prev = step1(prev, lo, upx, ub, v1, w.k_up);
                    }
                }
            }
        }
        __syncthreads();
        pin = xc[18];
    }

    // ---- Phase 3: replay short pre-collapse prefix with the true state ----
    #pragma unroll 1
    for (int tt = 0; tt < s; ++tt) {
        float lo, upx, ub, v1;
        mkconst(w, xc[tt], lo, upx, ub, v1);
        pin = step1(pin, lo, upx, ub, v1, w.k_up);
        xc[tt] = pin;
    }

    // ---- Warp-local coalesced store: warp w's chunks are final once its own
    //      lanes finish phase 3 (no block barrier needed) ----
    __syncwarp();
    {
        float* dst = out + rowbase + wid * WREG;
        #pragma unroll
        for (int i = 0; i < 4; ++i) {
            int tl = i * 128 + lane * 4;
            int c  = wid * 32 + (tl >> 4);
            int o  = tl & 15;
            float4 v = *(const float4*)(s_buf + c * PAD + o);
            *(float4*)(dst + tl) = v;
        }
    }
}

extern "C" void kernel_launch(void* const* d_in, const int* in_sizes, int n_in,
                              void* d_out, int out_size)
{
    const float* x  = (const float*)d_in[0];  // (B, T, 1) fp32
    const float* p0 = (const float*)d_in[1];  // (B, 1, 1) fp32
    const float* wv = (const float*)d_in[2];  // (4,)      fp32
    float* out = (float*)d_out;

    const int B = in_sizes[1];      // 2048
    const int T = in_sizes[0] / B;  // 8192  (= NT * CL)

    backlash_chunks<<<B, NT>>>(x, p0, wv, out, T);
}

// round 12
// speedup vs baseline: 1.0570x; 1.0010x over previous
#include <cuda_runtime.h>
#include <cstdint>
#include <cstddef>

// BacklashNet chunk-parallel scan: warp-decoupled SMEM staging, interval collapse.
//   lo = fl(fl(m_lo*x) + fl(m_lo*c_lo)), upx = fl(m_up*x), ub = fl(upx + k_up)
//   f1 = (prev >= lo);  f2 = (fl(prev - upx) <= k_up)
//   out = f1 ? (f2 ? fl(fl(lo+upx)+k_up) : lo) : (f2 ? ub : prev)
// Identity branch needs prev in (ub*, lo): interval-tracked until it provably
// collapses to one value -> chunk outputs become state-independent.

#define NT   512          // threads per block = chunks per row
#define CL   16           // steps per chunk (T = NT*CL = 8192)
#define PAD  20           // smem floats per chunk: 80B stride, 16B aligned;
                          //   conflict-free for 128-bit LDS/STS; slots [16..19]
#define WREG 512          // floats per warp region (32 lanes * CL)

struct Wt { float m_lo, m_up, k_lo, k_up; };

__device__ __forceinline__ uint32_t smem_u32(const void* p) {
    return (uint32_t)__cvta_generic_to_shared(p);
}
__device__ __forceinline__ void cp_async16(uint32_t dst, const float* src) {
    asm volatile("cp.async.ca.shared.global [%0], [%1], 16;\n" :: "r"(dst), "l"(src));
}

__device__ __forceinline__ bool f2_pred(float p, float upx, float k_up) {
    return __fadd_rn(p, -upx) <= k_up;          // fl(p - upx) <= k_up (monotone in p)
}
__device__ __forceinline__ void mkconst(const Wt& w, float xv,
                                        float& lo, float& upx, float& ub, float& v1) {
    float mlx = __fmul_rn(w.m_lo, xv);
    upx = __fmul_rn(w.m_up, xv);
    lo  = __fadd_rn(mlx, w.k_lo);
    ub  = __fadd_rn(upx, w.k_up);
    v1  = __fadd_rn(__fadd_rn(lo, upx), w.k_up); // reference's left-assoc sum
}
__device__ __forceinline__ float step1(float p, float lo, float upx, float ub,
                                       float v1, float k_up) {
    bool f1 = (p >= lo);
    bool f2 = f2_pred(p, upx, k_up);
    float a = f2 ? v1 : lo;
    float b = f2 ? ub : p;
    return f1 ? a : b;
}

__global__ __launch_bounds__(NT, 3)
void backlash_chunks(const float* __restrict__ x,
                     const float* __restrict__ p0,
                     const float* __restrict__ wv,
                     float* __restrict__ out, int T)
{
    __shared__ float s_buf[NT * PAD];   // chunk data + pad slots:
                                        //   xc[16]=cv  xc[17]=sx(int)  xc[18]=in

    const int k    = threadIdx.x;
    const int wid  = k >> 5;            // warp id (0..15)
    const int lane = k & 31;

    Wt w;
    w.m_lo = wv[0];
    w.m_up = wv[1];
    w.k_lo = __fmul_rn(w.m_lo, wv[2]);
    w.k_up = __fmul_rn(w.m_up, wv[3]);

    const size_t rowbase = (size_t)blockIdx.x * T;

    // ---- Warp-local coalesced staged load: warp w owns chunks [32w, 32w+32) ----
    {
        const float* src = x + rowbase + wid * WREG;
        const uint32_t sb = smem_u32(s_buf);
        #pragma unroll
        for (int i = 0; i < 4; ++i) {
            int tl = i * 128 + lane * 4;            // [0, 512) within warp region
            int c  = wid * 32 + (tl >> 4);
            int o  = tl & 15;
            cp_async16(sb + (uint32_t)(c * PAD + o) * 4u, src + tl);
        }
        asm volatile("cp.async.commit_group;\n" ::: "memory");
        asm volatile("cp.async.wait_group 0;\n" ::: "memory");
        __syncwarp();   // make cp.async data visible across the warp's lanes
    }

    float* xc = s_buf + k * PAD;        // this thread's chunk (in; becomes out)
    const float INF = __int_as_float(0x7f800000);

    // ---- Phase 1a: interval scan until collapse (float4 group loads, no stores) ----
    float A = -INF, Bv = INF;
    float p = 0.0f;
    bool  done = false;
    int   s = CL;

    #pragma unroll 1
    for (int t4 = 0; t4 < CL && !done; t4 += 4) {
        float4 q = *(const float4*)(xc + t4);
        float xs[4] = {q.x, q.y, q.z, q.w};
        #pragma unroll
        for (int j = 0; j < 4; ++j) {
            if (!done) {
                float lo, upx, ub, v1;
                mkconst(w, xs[j], lo, upx, ub, v1);
                // Region reachability over [A,Bv] via exact predicate evals.
                // ps = fminf(Bv, lo): conservative (<=1 ulp) identity hull top;
                // survival test at ps can only over-keep (sound).
                float mAlo = fmaxf(A, lo);
                float ps   = fminf(Bv, lo);
                bool aL = (A < lo);
                bool c1 = (mAlo <= Bv) &&  f2_pred(mAlo, upx, w.k_up); // f1& f2 -> v1
                bool c2 = (Bv >= lo)   && !f2_pred(Bv,   upx, w.k_up); // f1&!f2 -> lo
                bool c3 = aL           &&  f2_pred(A,    upx, w.k_up); //!f1& f2 -> ub
                bool c4 = aL           && !f2_pred(ps,   upx, w.k_up); // identity
                float nA = INF, nB = -INF;
                if (c1) { nA = fminf(nA, v1); nB = fmaxf(nB, v1); }
                if (c2) { nA = fminf(nA, lo); nB = fmaxf(nB, lo); }
                if (c3) { nA = fminf(nA, ub); nB = fmaxf(nB, ub); }
                if (c4) { nA = fminf(nA, A);  nB = fmaxf(nB, ps); }
                A = nA; Bv = nB;
                if (A == Bv) { done = true; p = A; s = t4 + j; }
            }
        }
    }

    // ---- Phase 1b: concrete scan, in-place stores for t >= s ----
    // Partial group (contains s..): one conflict-free LDS.128, predicated scalar
    // stores only for indices in (s, group end). Inputs at idx < s stay intact.
    if (done) {
        xc[s] = p;                                 // single scalar store
        int gb = (s + 1) & ~3;                     // base of group holding s+1
        if ((s + 1) & 3) {                         // partial group exists
            float4 q = *(const float4*)(xc + gb);  // mixed in/out; out never read
            float xs[4] = {q.x, q.y, q.z, q.w};
            #pragma unroll
            for (int j = 0; j < 4; ++j) {
                int idx = gb + j;
                if (idx > s && idx < CL) {
                    float lo, upx, ub, v1;
                    mkconst(w, xs[j], lo, upx, ub, v1);
                    p = step1(p, lo, upx, ub, v1, w.k_up);
                    xc[idx] = p;
                }
            }
            gb += 4;
        }
        #pragma unroll 1
        for (int u = gb; u < CL; u += 4) {
            float4 q = *(const float4*)(xc + u);
            float lo, upx, ub, v1;
            mkconst(w, q.x, lo, upx, ub, v1);
            float o0 = step1(p,  lo, upx, ub, v1, w.k_up);
            mkconst(w, q.y, lo, upx, ub, v1);
            float o1 = step1(o0, lo, upx, ub, v1, w.k_up);
            mkconst(w, q.z, lo, upx, ub, v1);
            float o2 = step1(o1, lo, upx, ub, v1, w.k_up);
            mkconst(w, q.w, lo, upx, ub, v1);
            float o3 = step1(o2, lo, upx, ub, v1, w.k_up);
            p = o3;
            *(float4*)(xc + u) = make_float4(o0, o1, o2, o3);
        }
    }

    // ---- Phase 2: inter-chunk resolution (pad-slot side channel) ----
    xc[16] = p;                                  // collapsed end value
    reinterpret_cast<int*>(xc)[17] = s;          // collapse index
    bool all = (bool)__syncthreads_and((int)done);   // block-uniform barrier
    float pin;
    if (all) {
        pin = (k == 0) ? p0[blockIdx.x] : s_buf[(k - 1) * PAD + 16];
    } else {
        if (k == 0) {                             // rare serial fallback
            float prev = p0[blockIdx.x];
            for (int c = 0; c < NT; ++c) {
                float* xr = s_buf + c * PAD;
                xr[18] = prev;
                if (reinterpret_cast<int*>(xr)[17] < CL) {
                    prev = xr[16];
                } else {                          // chunk input untouched
                    for (int tt = 0; tt < CL; ++tt) {
                        float lo, upx, ub, v1;
                        mkconst(w, xr[tt], lo, upx, ub, v1);
                        prev = step1(prev, lo, upx, ub, v1, w.k_up);
                    }
                }
            }
        }
        __syncthreads();
        pin = xc[18];
    }

    // ---- Phase 3: replay pre-collapse prefix, vectorized SMEM access ----
    // Group loads are safe: elements with idx >= s are outputs, never consumed.
    #pragma unroll 1
    for (int t4 = 0; t4 < s; t4 += 4) {
        float4 q = *(const float4*)(xc + t4);
        float xs[4] = {q.x, q.y, q.z, q.w};
        float ov[4];
        #pragma unroll
        for (int j = 0; j < 4; ++j) {
            if (t4 + j < s) {
                float lo, upx, ub, v1;
                mkconst(w, xs[j], lo, upx, ub, v1);
                pin = step1(pin, lo, upx, ub, v1, w.k_up);
            }
            ov[j] = pin;              // idx >= s lanes: value unused
        }
        if (t4 + 4 <= s) {            // full group -> conflict-free STS.128
            *(float4*)(xc + t4) = make_float4(ov[0], ov[1], ov[2], ov[3]);
        } else {                      // final partial group -> scalar stores
            #pragma unroll
            for (int j = 0; j < 4; ++j)
                if (t4 + j < s) xc[t4 + j] = ov[j];
        }
    }

    // ---- Warp-local coalesced store: warp w's chunks are final once its own
    //      lanes finish phase 3 (no block barrier needed) ----
    __syncwarp();
    {
        float* dst = out + rowbase + wid * WREG;
        #pragma unroll
        for (int i = 0; i < 4; ++i) {
            int tl = i * 128 + lane * 4;
            int c  = wid * 32 + (tl >> 4);
            int o  = tl & 15;
            float4 v = *(const float4*)(s_buf + c * PAD + o);
            *(float4*)(dst + tl) = v;
        }
    }
}

extern "C" void kernel_launch(void* const* d_in, const int* in_sizes, int n_in,
                              void* d_out, int out_size)
{
    const float* x  = (const float*)d_in[0];  // (B, T, 1) fp32
    const float* p0 = (const float*)d_in[1];  // (B, 1, 1) fp32
    const float* wv = (const float*)d_in[2];  // (4,)      fp32
    float* out = (float*)d_out;

    const int B = in_sizes[1];      // 2048
    const int T = in_sizes[0] / B;  // 8192  (= NT * CL)

    backlash_chunks<<<B, NT>>>(x, p0, wv, out, T);
}